// round 14
// baseline (speedup 1.0000x reference)
#include <cuda_runtime.h>
#include <cuda_fp16.h>
#include <cstdint>

#define TDIM 2048
#define DDIM 64
#define BH 32
#define BQ 64
#define BK 64
#define NTH 128
#define KTILES (TDIM / BK)

#define NELEM ((size_t)BH * TDIM * DDIM)
// fragment tensors: [bh][kt][ksnp(16)][lane(32)] x 16B
#define NFRAG ((size_t)BH * KTILES * 16 * 32)

__device__ unsigned int g_maskbits[(size_t)TDIM * TDIM / 32];  // 512 KB
__device__ uint4 g_qh[NELEM / 8];     // Q fp16 row-major (scaled)
__device__ uint4 g_kf[NFRAG];         // K in B-fragment order (8 MB)
__device__ uint4 g_vf[NFRAG];         // V^T in B-fragment order (8 MB)

// ---------------- helpers ----------------
// fp16 MMA, fp32 accumulate
__device__ __forceinline__ void mma16816(float (&c)[4], const uint32_t (&a)[4],
                                         uint32_t b0, uint32_t b1) {
    asm volatile(
        "mma.sync.aligned.m16n8k16.row.col.f32.f16.f16.f32 "
        "{%0,%1,%2,%3}, {%4,%5,%6,%7}, {%8,%9}, {%0,%1,%2,%3};"
        : "+f"(c[0]), "+f"(c[1]), "+f"(c[2]), "+f"(c[3])
        : "r"(a[0]), "r"(a[1]), "r"(a[2]), "r"(a[3]), "r"(b0), "r"(b1));
}
__device__ __forceinline__ float ex2f(float x) {
    float r;
    asm("ex2.approx.f32 %0, %1;" : "=f"(r) : "f"(x));
    return r;
}
// pack two fp32 into fp16x2 (lo=x, hi=y) — single CVT
__device__ __forceinline__ uint32_t pack_h2(float x, float y) {
    uint32_t r;
    asm("cvt.rn.f16x2.f32 %0, %1, %2;" : "=r"(r) : "f"(y), "f"(x));
    return r;
}
__device__ __forceinline__ uint32_t pack_us(ushort lo, ushort hi) {
    return ((uint32_t)hi << 16) | lo;
}

// ---------------- prepass kernels ----------------
__global__ void pack_mask(const int* __restrict__ m) {
    int w = blockIdx.x * blockDim.x + threadIdx.x;
    if (w >= (TDIM * TDIM) / 32) return;
    const int4* p = (const int4*)(m + (size_t)w * 32);
    unsigned int bits = 0;
    #pragma unroll
    for (int i = 0; i < 8; ++i) {
        int4 v = p[i];
        bits |= (unsigned)(v.x != 0) << (i * 4);
        bits |= (unsigned)(v.y != 0) << (i * 4 + 1);
        bits |= (unsigned)(v.z != 0) << (i * 4 + 2);
        bits |= (unsigned)(v.w != 0) << (i * 4 + 3);
    }
    g_maskbits[w] = bits;
}

// fp32 -> fp16 (8 elems/thread), with scale (Q only)
__global__ void cvt_f16(const float4* __restrict__ src, uint4* __restrict__ dst,
                        float scale, int n16) {
    int i = blockIdx.x * blockDim.x + threadIdx.x;
    if (i >= n16) return;
    float4 a = src[2 * i], b = src[2 * i + 1];
    uint4 w;
    w.x = pack_h2(a.x * scale, a.y * scale);
    w.y = pack_h2(a.z * scale, a.w * scale);
    w.z = pack_h2(b.x * scale, b.y * scale);
    w.w = pack_h2(b.z * scale, b.w * scale);
    dst[i] = w;
}

// Gather one 64x64 K tile into B-fragment order.
// Frag (ks,np), lane (g = lane>>2, tq = lane&3):
//   w.x = K[n0  ][k0], K[n0  ][k0+1]   (n0 = np*16+g, k0 = ks*16+2tq)
//   w.y = K[n0  ][k0+8], +9
//   w.z = K[n0+8][k0], +1
//   w.w = K[n0+8][k0+8], +9
__global__ void kfrag_gather(const float* __restrict__ ksrc, uint4* __restrict__ dstf) {
    __shared__ ushort sm[64 * 64];
    const int kt = blockIdx.x, bh = blockIdx.y;
    const int tid = threadIdx.x;
    const float4* src = (const float4*)(ksrc + ((size_t)bh * TDIM + (size_t)kt * BK) * DDIM);
    #pragma unroll
    for (int it = 0; it < 8; ++it) {
        int idx = tid + it * NTH;            // 1024 float4
        float4 v = src[idx];
        int base = idx * 4;                  // element offset in [64][64]
        sm[base]     = __half_as_ushort(__float2half_rn(v.x));
        sm[base + 1] = __half_as_ushort(__float2half_rn(v.y));
        sm[base + 2] = __half_as_ushort(__float2half_rn(v.z));
        sm[base + 3] = __half_as_ushort(__float2half_rn(v.w));
    }
    __syncthreads();
    uint4* out = dstf + ((size_t)bh * KTILES + kt) * 16 * 32;
    #pragma unroll
    for (int i = 0; i < 4; ++i) {
        int pos = tid + i * NTH;             // 512 positions
        int ksnp = pos >> 5, lane = pos & 31;
        int ks = ksnp >> 2, np = ksnp & 3;
        int g = lane >> 2, tq = lane & 3;
        int n0 = np * 16 + g, k0 = ks * 16 + 2 * tq;
        uint4 w;
        w.x = pack_us(sm[n0 * 64 + k0],           sm[n0 * 64 + k0 + 1]);
        w.y = pack_us(sm[n0 * 64 + k0 + 8],       sm[n0 * 64 + k0 + 9]);
        w.z = pack_us(sm[(n0 + 8) * 64 + k0],     sm[(n0 + 8) * 64 + k0 + 1]);
        w.w = pack_us(sm[(n0 + 8) * 64 + k0 + 8], sm[(n0 + 8) * 64 + k0 + 9]);
        out[pos] = w;
    }
}

// Gather one 64x64 V tile (transposed role: B[k=tok][n=d]) into fragment order.
//   w.x = V[t0  ][d0], V[t0+1][d0]      (t0 = ks*16+2tq, d0 = np*16+g)
//   w.y = V[t0+8][d0], V[t0+9][d0]
//   w.z = V[t0  ][d0+8], V[t0+1][d0+8]
//   w.w = V[t0+8][d0+8], V[t0+9][d0+8]
__global__ void vfrag_gather(const float* __restrict__ vsrc, uint4* __restrict__ dstf) {
    __shared__ ushort sm[64 * 64];
    const int kt = blockIdx.x, bh = blockIdx.y;
    const int tid = threadIdx.x;
    const float4* src = (const float4*)(vsrc + ((size_t)bh * TDIM + (size_t)kt * BK) * DDIM);
    #pragma unroll
    for (int it = 0; it < 8; ++it) {
        int idx = tid + it * NTH;
        float4 v = src[idx];
        int base = idx * 4;
        sm[base]     = __half_as_ushort(__float2half_rn(v.x));
        sm[base + 1] = __half_as_ushort(__float2half_rn(v.y));
        sm[base + 2] = __half_as_ushort(__float2half_rn(v.z));
        sm[base + 3] = __half_as_ushort(__float2half_rn(v.w));
    }
    __syncthreads();
    uint4* out = dstf + ((size_t)bh * KTILES + kt) * 16 * 32;
    #pragma unroll
    for (int i = 0; i < 4; ++i) {
        int pos = tid + i * NTH;
        int ksnp = pos >> 5, lane = pos & 31;
        int ks = ksnp >> 2, np = ksnp & 3;
        int g = lane >> 2, tq = lane & 3;
        int t0 = ks * 16 + 2 * tq, d0 = np * 16 + g;
        uint4 w;
        w.x = pack_us(sm[t0 * 64 + d0],           sm[(t0 + 1) * 64 + d0]);
        w.y = pack_us(sm[(t0 + 8) * 64 + d0],     sm[(t0 + 9) * 64 + d0]);
        w.z = pack_us(sm[t0 * 64 + d0 + 8],       sm[(t0 + 1) * 64 + d0 + 8]);
        w.w = pack_us(sm[(t0 + 8) * 64 + d0 + 8], sm[(t0 + 9) * 64 + d0 + 8]);
        out[pos] = w;
    }
}

// -------- main kernel: fully smem-free, barrier-free, independent warps --------
__global__ __launch_bounds__(NTH, 4)
void fa_mma(float* __restrict__ go)
{
    const int tid = threadIdx.x;
    const int lane = tid & 31, wid = tid >> 5;
    const int bh = blockIdx.y;
    const int q0 = blockIdx.x * BQ;
    const int m0 = wid * 16;

    const int g  = lane >> 2;
    const int tq = lane & 3;
    const int r0loc = m0 + g;

    const size_t row_bytes = 128;
    const char* gqh = (const char*)g_qh + ((size_t)bh * TDIM + q0) * row_bytes;
    const uint4* kf = g_kf + (size_t)bh * KTILES * 16 * 32 + lane;
    const uint4* vf = g_vf + (size_t)bh * KTILES * 16 * 32 + lane;
    float* ob = go + (size_t)bh * TDIM * DDIM;

    // ---- Q fragments straight from global (A-frag = 2 consecutive fp16) ----
    uint32_t aQ[4][4];
    #pragma unroll
    for (int ks = 0; ks < 4; ++ks) {
        uint32_t cb = ks * 32 + tq * 4;
        const char* r0h = gqh + (size_t)r0loc * 128;
        const char* r1h = gqh + (size_t)(r0loc + 8) * 128;
        aQ[ks][0] = *(const uint32_t*)(r0h + cb);
        aQ[ks][1] = *(const uint32_t*)(r1h + cb);
        aQ[ks][2] = *(const uint32_t*)(r0h + cb + 16);
        aQ[ks][3] = *(const uint32_t*)(r1h + cb + 16);
    }

    float oreg[8][4];
    #pragma unroll
    for (int i = 0; i < 8; ++i)
        #pragma unroll
        for (int j = 0; j < 4; ++j) oreg[i][j] = 0.f;
    float lsum0 = 0.f, lsum1 = 0.f;

    for (int kt = 0; kt < KTILES; ++kt) {
        // early mask fetch (independent LDG)
        unsigned long long mw0 =
            *(const unsigned long long*)(g_maskbits + (size_t)(q0 + r0loc) * (TDIM / 32) + kt * 2);
        unsigned long long mw1 =
            *(const unsigned long long*)(g_maskbits + (size_t)(q0 + r0loc + 8) * (TDIM / 32) + kt * 2);

        const uint4* kft = kf + (size_t)kt * 16 * 32;
        const uint4* vft = vf + (size_t)kt * 16 * 32;

        // ---- S = Q K^T (single-term fp16), B frags via coalesced LDG.128 ----
        float s[8][4];
        #pragma unroll
        for (int i = 0; i < 8; ++i)
            #pragma unroll
            for (int j = 0; j < 4; ++j) s[i][j] = 0.f;

        #pragma unroll
        for (int ks = 0; ks < 4; ++ks) {
            uint4 bK[4];
            #pragma unroll
            for (int np = 0; np < 4; ++np)
                bK[np] = kft[(ks * 4 + np) * 32];
            #pragma unroll
            for (int np = 0; np < 4; ++np) {
                mma16816(s[2 * np],     aQ[ks], bK[np].x, bK[np].y);
                mma16816(s[2 * np + 1], aQ[ks], bK[np].z, bK[np].w);
            }
        }

        // ---- mask + exp2 -> register-resident P (A-frag layout) ----
        uint32_t aP[4][4];
        #pragma unroll
        for (int ks = 0; ks < 4; ++ks) {
            #pragma unroll
            for (int h = 0; h < 2; ++h) {          // n8-tile 2ks+h
                int ng = 2 * ks + h;
                int c = ng * 8 + tq * 2;
                float p0 = ((mw0 >> c) & 1ULL)       ? 0.f : ex2f(s[ng][0]);
                float p1 = ((mw0 >> (c + 1)) & 1ULL) ? 0.f : ex2f(s[ng][1]);
                float p2 = ((mw1 >> c) & 1ULL)       ? 0.f : ex2f(s[ng][2]);
                float p3 = ((mw1 >> (c + 1)) & 1ULL) ? 0.f : ex2f(s[ng][3]);
                lsum0 += p0 + p1;
                lsum1 += p2 + p3;
                aP[ks][2 * h]     = pack_h2(p0, p1);   // row g
                aP[ks][2 * h + 1] = pack_h2(p2, p3);   // row g+8
            }
        }

        // ---- O += P V (single-term fp16), V frags via coalesced LDG.128 ----
        #pragma unroll
        for (int ks = 0; ks < 4; ++ks) {
            uint4 bV[4];
            #pragma unroll
            for (int np = 0; np < 4; ++np)
                bV[np] = vft[(ks * 4 + np) * 32];
            #pragma unroll
            for (int np = 0; np < 4; ++np) {
                mma16816(oreg[2 * np],     aP[ks], bV[np].x, bV[np].y);
                mma16816(oreg[2 * np + 1], aP[ks], bV[np].z, bV[np].w);
            }
        }
    }

    // ---- epilogue ----
    #pragma unroll
    for (int off = 1; off <= 2; off <<= 1) {
        lsum0 += __shfl_xor_sync(0xffffffffu, lsum0, off);
        lsum1 += __shfl_xor_sync(0xffffffffu, lsum1, off);
    }
    float inv0 = 1.f / lsum0;
    float inv1 = 1.f / lsum1;

    float* orow0 = ob + (size_t)(q0 + r0loc) * DDIM;
    float* orow1 = ob + (size_t)(q0 + r0loc + 8) * DDIM;
    #pragma unroll
    for (int ng = 0; ng < 8; ++ng) {
        int c = ng * 8 + tq * 2;
        *(float2*)(orow0 + c) = make_float2(oreg[ng][0] * inv0, oreg[ng][1] * inv0);
        *(float2*)(orow1 + c) = make_float2(oreg[ng][2] * inv1, oreg[ng][3] * inv1);
    }
}

extern "C" void kernel_launch(void* const* d_in, const int* in_sizes, int n_in,
                              void* d_out, int out_size) {
    const float* q = (const float*)d_in[0];
    const float* k = (const float*)d_in[1];
    const float* v = (const float*)d_in[2];
    const int* mask = (const int*)d_in[3];
    float* out = (float*)d_out;

    uint4 *qh, *kfp, *vfp;
    cudaGetSymbolAddress((void**)&qh, g_qh);
    cudaGetSymbolAddress((void**)&kfp, g_kf);
    cudaGetSymbolAddress((void**)&vfp, g_vf);

    pack_mask<<<(TDIM * TDIM / 32 + 255) / 256, 256>>>(mask);

    const int n16 = (int)(NELEM / 8);
    // Q scale folds softmax 1/sqrt(D) and log2(e): exp(s) == exp2(s*log2e)
    const float qscale = 0.125f * 1.44269504088896340736f;
    cvt_f16<<<(n16 + 255) / 256, 256>>>((const float4*)q, qh, qscale, n16);

    dim3 fgrid(KTILES, BH);
    kfrag_gather<<<fgrid, NTH>>>(k, kfp);
    vfrag_gather<<<fgrid, NTH>>>(v, vfp);

    dim3 grid(TDIM / BQ, BH);
    fa_mma<<<grid, NTH>>>(out);
}